// round 3
// baseline (speedup 1.0000x reference)
#include <cuda_runtime.h>

// Warping_65094524339056 — Round 3: SMEM tile staging.
//
// out[b,x,y,z] = trilinear(image[b], (x,y,z)+ddf[b,x,y,z,:]) with clamp [0,127].
//
// Block = 256 threads -> output tile 16(x) x 8(y) x 32(z) = 4096 voxels.
// Image tile with halo H=4 staged in SMEM: 25 x 17 x 41 floats = 68.1 KB.
// Gathers become LDS (lanes z-consecutive -> ~conflict-free); displacements
// are N(0,1) so out-of-halo samples (P ~ 2e-4) take a guarded global path.
// Image (33.5MB) fits in L2 (126MB) -> halo overfetch costs L2 only.

#define DMASK 127
#define H   4
#define OXB 16
#define OYB 8
#define OZB 32
#define EX  (OXB + 2*H + 1)   // 25
#define EY  (OYB + 2*H + 1)   // 17
#define EZ  (OZB + 2*H + 1)   // 41
#define TILE_ELEMS (EX*EY*EZ) // 17425
#define BLOCK 256
#define VPT  ((OXB*OYB*OZB)/BLOCK)  // 16

__device__ __forceinline__ float clampf(float v) {
    return fminf(fmaxf(v, 0.0f), 127.0f);
}

__global__ __launch_bounds__(BLOCK) void warp_kernel(
    const float* __restrict__ ddf,
    const float* __restrict__ image,
    float* __restrict__ out)
{
    extern __shared__ float tile[];

    int tid = threadIdx.x;
    int bid = blockIdx.x;
    // 8(x) x 16(y) x 4(z) tiles x 4 batches = 2048 blocks
    int tz = bid & 3;
    int ty = (bid >> 2) & 15;
    int tx = (bid >> 6) & 7;
    int b  = bid >> 9;

    int X0 = tx << 4;   // *16
    int Y0 = ty << 3;   // *8
    int Z0 = tz << 5;   // *32

    const float* img = image + ((long long)b << 21);

    // ---- stage image tile (+halo, clamped) into SMEM ----
    for (int i = tid; i < TILE_ELEMS; i += BLOCK) {
        int sz = i % EZ;
        int r  = i / EZ;
        int sy = r % EY;
        int sx = r / EY;
        int gx = min(max(X0 - H + sx, 0), DMASK);
        int gy = min(max(Y0 - H + sy, 0), DMASK);
        int gz = min(max(Z0 - H + sz, 0), DMASK);
        tile[i] = __ldg(img + (gx << 14) + (gy << 7) + gz);
    }
    __syncthreads();

    // ---- compute: 16 voxels per thread, lanes z-consecutive ----
#pragma unroll 4
    for (int v = 0; v < VPT; v++) {
        int id = tid + (v << 8);           // 0..4095
        int lz = id & 31;
        int ly = (id >> 5) & 7;
        int lx = id >> 8;                  // 0..15

        int x = X0 + lx;
        int y = Y0 + ly;
        int z = Z0 + lz;
        long long vid = ((long long)b << 21) + (x << 14) + (y << 7) + z;

        const float* dp = ddf + vid * 3;
        float dx = __ldg(dp);
        float dy = __ldg(dp + 1);
        float dz = __ldg(dp + 2);

        float fx = clampf((float)x + dx);
        float fy = clampf((float)y + dy);
        float fz = clampf((float)z + dz);

        int ix0 = (int)fx;
        int iy0 = (int)fy;
        int iz0 = (int)fz;
        float wx = fx - (float)ix0;
        float wy = fy - (float)iy0;
        float wz = fz - (float)iz0;
        int ix1 = min(ix0 + 1, DMASK);
        int iy1 = min(iy0 + 1, DMASK);
        int iz1 = min(iz0 + 1, DMASK);

        int sx0 = ix0 - X0 + H, sx1 = ix1 - X0 + H;
        int sy0 = iy0 - Y0 + H, sy1 = iy1 - Y0 + H;
        int sz0 = iz0 - Z0 + H, sz1 = iz1 - Z0 + H;

        bool ok = (sx0 >= 0) & (sx1 < EX) &
                  (sy0 >= 0) & (sy1 < EY) &
                  (sz0 >= 0) & (sz1 < EZ);

        float v000, v001, v010, v011, v100, v101, v110, v111;
        if (ok) {
            int r00 = (sx0 * EY + sy0) * EZ;
            int r01 = (sx0 * EY + sy1) * EZ;
            int r10 = (sx1 * EY + sy0) * EZ;
            int r11 = (sx1 * EY + sy1) * EZ;
            v000 = tile[r00 + sz0];  v001 = tile[r00 + sz1];
            v010 = tile[r01 + sz0];  v011 = tile[r01 + sz1];
            v100 = tile[r10 + sz0];  v101 = tile[r10 + sz1];
            v110 = tile[r11 + sz0];  v111 = tile[r11 + sz1];
        } else {
            // rare (~2e-4 of voxels): displacement beyond halo
            int g00 = (ix0 << 14) + (iy0 << 7);
            int g01 = (ix0 << 14) + (iy1 << 7);
            int g10 = (ix1 << 14) + (iy0 << 7);
            int g11 = (ix1 << 14) + (iy1 << 7);
            v000 = __ldg(img + g00 + iz0);  v001 = __ldg(img + g00 + iz1);
            v010 = __ldg(img + g01 + iz0);  v011 = __ldg(img + g01 + iz1);
            v100 = __ldg(img + g10 + iz0);  v101 = __ldg(img + g10 + iz1);
            v110 = __ldg(img + g11 + iz0);  v111 = __ldg(img + g11 + iz1);
        }

        float c00 = v000 + wz * (v001 - v000);
        float c01 = v010 + wz * (v011 - v010);
        float c10 = v100 + wz * (v101 - v100);
        float c11 = v110 + wz * (v111 - v110);
        float c0  = c00 + wy * (c01 - c00);
        float c1  = c10 + wy * (c11 - c10);
        out[vid]  = c0 + wx * (c1 - c0);
    }
}

extern "C" void kernel_launch(void* const* d_in, const int* in_sizes, int n_in,
                              void* d_out, int out_size)
{
    const float* ddf   = (const float*)d_in[0];
    const float* image = (const float*)d_in[1];
    float* out = (float*)d_out;

    size_t smem = TILE_ELEMS * sizeof(float);   // 69700 B
    cudaFuncSetAttribute(warp_kernel,
                         cudaFuncAttributeMaxDynamicSharedMemorySize, (int)smem);

    int grid = 2048;   // 8 x 16 x 4 tiles x 4 batches
    warp_kernel<<<grid, BLOCK, smem>>>(ddf, image, out);
}

// round 4
// speedup vs baseline: 1.4187x; 1.4187x over previous
#include <cuda_runtime.h>

// Warping_65094524339056 — Round 4: SMEM tile, 512 threads, clamp-baked tile,
// single-base LDS offsets, hoisted index math.
//
// Block = 512 threads -> output tile 16(x) x 8(y) x 32(z) = 4096 voxels (8/thread).
// Image tile with halo H=4 (+1 upper slot) staged in SMEM: 25 x 17 x 41 = 68.1 KB.
// Staging clamps coords to [0,127], so the +1 corner offsets inside the tile are
// automatically clamp-correct -> in-tile path uses base + const offsets only.

#define DMASK 127
#define H   4
#define OXB 16
#define OYB 8
#define OZB 32
#define EX  (OXB + 2*H + 1)   // 25
#define EY  (OYB + 2*H + 1)   // 17
#define EZ  (OZB + 2*H + 1)   // 41
#define TILE_ELEMS (EX*EY*EZ) // 17425
#define BLOCK 512
#define VPT  8
#define SXY  (EY*EZ)          // 697

__device__ __forceinline__ float clampf(float v) {
    return fminf(fmaxf(v, 0.0f), 127.0f);
}

__global__ __launch_bounds__(BLOCK) void warp_kernel(
    const float* __restrict__ ddf,
    const float* __restrict__ image,
    float* __restrict__ out)
{
    extern __shared__ float tile[];

    int tid = threadIdx.x;
    int bid = blockIdx.x;
    // 8(x) x 16(y) x 4(z) tiles x 4 batches = 2048 blocks
    int tz = bid & 3;
    int ty = (bid >> 2) & 15;
    int tx = (bid >> 6) & 7;
    int b  = bid >> 9;

    int X0 = tx << 4;
    int Y0 = ty << 3;
    int Z0 = tz << 5;

    const float* img = image + ((long long)b << 21);

    // ---- stage image tile (+halo, clamped) into SMEM ----
    for (int i = tid; i < TILE_ELEMS; i += BLOCK) {
        int sz = i % EZ;
        int r  = i / EZ;
        int sy = r % EY;
        int sx = r / EY;
        int gx = min(max(X0 - H + sx, 0), DMASK);
        int gy = min(max(Y0 - H + sy, 0), DMASK);
        int gz = min(max(Z0 - H + sz, 0), DMASK);
        tile[i] = __ldg(img + (gx << 14) + (gy << 7) + gz);
    }
    __syncthreads();

    // ---- fixed per-thread coords: z,y fixed; x = X0 + 2v + (tid>>8) ----
    int lz  = tid & 31;
    int ly  = (tid >> 5) & 7;
    int lxh = tid >> 8;                 // 0 or 1
    int y = Y0 + ly;
    int z = Z0 + lz;

    int xb = X0 + lxh;
    long long vid0 = ((long long)b << 21) + ((long long)xb << 14) + (y << 7) + z;
    const long long VSTRIDE = 2LL << 14;          // x += 2 per iteration

    // precompute tile-frame origins
    int ox = X0 - H;     // ix0 - ox = sx0
    int oy = Y0 - H;
    int oz = Z0 - H;

    float xf = (float)xb;

#pragma unroll
    for (int v = 0; v < VPT; v++) {
        long long vid = vid0 + (long long)v * VSTRIDE;

        const float* dp = ddf + vid * 3;
        float dx = __ldg(dp);
        float dy = __ldg(dp + 1);
        float dz = __ldg(dp + 2);

        float fx = clampf(xf + 2.0f * v + dx);
        float fy = clampf((float)y + dy);
        float fz = clampf((float)z + dz);

        int ix0 = (int)fx;
        int iy0 = (int)fy;
        int iz0 = (int)fz;
        float wx = fx - (float)ix0;
        float wy = fy - (float)iy0;
        float wz = fz - (float)iz0;

        int sx0 = ix0 - ox;
        int sy0 = iy0 - oy;
        int sz0 = iz0 - oz;

        bool ok = ((unsigned)sx0 <= (unsigned)(EX - 2)) &
                  ((unsigned)sy0 <= (unsigned)(EY - 2)) &
                  ((unsigned)sz0 <= (unsigned)(EZ - 2));

        float v000, v001, v010, v011, v100, v101, v110, v111;
        if (ok) {
            int base = (sx0 * EY + sy0) * EZ + sz0;
            v000 = tile[base];
            v001 = tile[base + 1];
            v010 = tile[base + EZ];
            v011 = tile[base + EZ + 1];
            v100 = tile[base + SXY];
            v101 = tile[base + SXY + 1];
            v110 = tile[base + SXY + EZ];
            v111 = tile[base + SXY + EZ + 1];
        } else {
            // rare: displacement beyond halo -> clamped global gather
            int ix1 = min(ix0 + 1, DMASK);
            int iy1 = min(iy0 + 1, DMASK);
            int iz1 = min(iz0 + 1, DMASK);
            int g00 = (ix0 << 14) + (iy0 << 7);
            int g01 = (ix0 << 14) + (iy1 << 7);
            int g10 = (ix1 << 14) + (iy0 << 7);
            int g11 = (ix1 << 14) + (iy1 << 7);
            v000 = __ldg(img + g00 + iz0);  v001 = __ldg(img + g00 + iz1);
            v010 = __ldg(img + g01 + iz0);  v011 = __ldg(img + g01 + iz1);
            v100 = __ldg(img + g10 + iz0);  v101 = __ldg(img + g10 + iz1);
            v110 = __ldg(img + g11 + iz0);  v111 = __ldg(img + g11 + iz1);
        }

        float c00 = v000 + wz * (v001 - v000);
        float c01 = v010 + wz * (v011 - v010);
        float c10 = v100 + wz * (v101 - v100);
        float c11 = v110 + wz * (v111 - v110);
        float c0  = c00 + wy * (c01 - c00);
        float c1  = c10 + wy * (c11 - c10);
        out[vid]  = c0 + wx * (c1 - c0);
    }
}

extern "C" void kernel_launch(void* const* d_in, const int* in_sizes, int n_in,
                              void* d_out, int out_size)
{
    const float* ddf   = (const float*)d_in[0];
    const float* image = (const float*)d_in[1];
    float* out = (float*)d_out;

    size_t smem = TILE_ELEMS * sizeof(float);   // 69700 B
    cudaFuncSetAttribute(warp_kernel,
                         cudaFuncAttributeMaxDynamicSharedMemorySize, (int)smem);

    int grid = 2048;
    warp_kernel<<<grid, BLOCK, smem>>>(ddf, image, out);
}

// round 5
// speedup vs baseline: 1.8647x; 1.3144x over previous
#include <cuda_runtime.h>

// Warping_65094524339056 — Round 5: lean SMEM tile kernel.
//
// out[b,x,y,z] = trilinear(image[b], (x,y,z)+ddf[b,x,y,z,:]), clamp [0,127].
//
// Tile: output 16(x) x 8(y) x 32(z) per 512-thread block; image tile with
// halo 4 (+1) staged in SMEM as 25 x 17 x 41 (z-stride padded to 42) = 71.4KB
// -> 3 blocks/SM, 48 warps.
//
// Key points:
//  * Staging: warp-per-row; sx/sy/gx/gy are warp-uniform, lanes take
//    consecutive z. Border clamping baked into the tile (duplicated rows).
//  * Compute: NO clamps. fx = x+dx (same fp as reference), floor via
//    __float2int_rd. If the floor cell is inside the halo, unclamped
//    interpolation over the clamp-duplicated tile is bitwise-equal to the
//    clamped reference. Out-of-halo (~2e-4 of voxels) -> clamped global path.

#define DMASK 127
#define H    4
#define EX   25
#define EY   17
#define EZV  41          // valid z slots
#define SZ   42          // padded z stride
#define SXY  (EY*SZ)     // 714
#define TILE_ELEMS (EX*SXY)  // 17850 floats = 71.4 KB
#define NROWS (EX*EY)    // 425
#define BLOCK 512
#define VPT   8

__device__ __forceinline__ float clampf(float v) {
    return fminf(fmaxf(v, 0.0f), 127.0f);
}

__global__ __launch_bounds__(BLOCK) void warp_kernel(
    const float* __restrict__ ddf,
    const float* __restrict__ image,
    float* __restrict__ out)
{
    extern __shared__ float tile[];

    int tid = threadIdx.x;
    int bid = blockIdx.x;
    // 8(x) x 16(y) x 4(z) tiles x 4 batches = 2048 blocks
    int tz = bid & 3;
    int ty = (bid >> 2) & 15;
    int tx = (bid >> 6) & 7;
    int b  = bid >> 9;

    int X0 = tx << 4;
    int Y0 = ty << 3;
    int Z0 = tz << 5;

    const float* img = image + ((long long)b << 21);

    // ---- stage tile: one row per warp per step; clamps are warp-uniform ----
    {
        int wid  = tid >> 5;
        int lane = tid & 31;
        for (int r = wid; r < NROWS; r += 16) {
            int sy = r % EY;
            int sx = r / EY;
            int gx = min(max(X0 - H + sx, 0), DMASK);
            int gy = min(max(Y0 - H + sy, 0), DMASK);
            const float* rowp = img + (gx << 14) + (gy << 7);
            float* srow = tile + r * SZ;
            int gz0 = max(Z0 - H + lane, 0);          // upper never exceeds 123
            srow[lane] = __ldg(rowp + gz0);
            if (lane < EZV - 32) {                    // 9 tail elements
                int gz1 = min(Z0 - H + 32 + lane, DMASK);
                srow[lane + 32] = __ldg(rowp + gz1);
            }
        }
    }
    __syncthreads();

    // ---- compute: 8 voxels/thread; lanes are z-consecutive ----
    int lz  = tid & 31;
    int ly  = (tid >> 5) & 7;
    int lxh = tid >> 8;                // 0 or 1; x = X0 + lxh + 2*v

    int y = Y0 + ly;
    int z = Z0 + lz;
    int xb = X0 + lxh;

    int vid0 = (xb << 14) + (y << 7) + z;          // within-batch offset
    const float* ddfb = ddf + ((long long)b << 21) * 3;
    float*       outb = out + ((long long)b << 21);

    const float yf = (float)y;
    const float zf = (float)z;
    const int ox = X0 - H, oy = Y0 - H, oz = Z0 - H;

#pragma unroll
    for (int v = 0; v < VPT; v++) {
        int vid = vid0 + (v << 15);                // x += 2 per iter

        const float* dp = ddfb + (long long)vid * 3;
        float dx = __ldg(dp);
        float dy = __ldg(dp + 1);
        float dz = __ldg(dp + 2);

        float fx = (float)(xb + 2 * v) + dx;       // same fp as reference
        float fy = yf + dy;
        float fz = zf + dz;

        int ix0 = __float2int_rd(fx);
        int iy0 = __float2int_rd(fy);
        int iz0 = __float2int_rd(fz);
        float wx = fx - (float)ix0;
        float wy = fy - (float)iy0;
        float wz = fz - (float)iz0;

        int sx0 = ix0 - ox;
        int sy0 = iy0 - oy;
        int sz0 = iz0 - oz;

        bool ok = ((unsigned)sx0 <= (unsigned)(EX - 2)) &
                  ((unsigned)sy0 <= (unsigned)(EY - 2)) &
                  ((unsigned)sz0 <= (unsigned)(EZV - 2));

        float v000, v001, v010, v011, v100, v101, v110, v111;
        if (ok) {
            int base = (sx0 * EY + sy0) * SZ + sz0;
            v000 = tile[base];
            v001 = tile[base + 1];
            v010 = tile[base + SZ];
            v011 = tile[base + SZ + 1];
            v100 = tile[base + SXY];
            v101 = tile[base + SXY + 1];
            v110 = tile[base + SXY + SZ];
            v111 = tile[base + SXY + SZ + 1];
        } else {
            // rare: beyond halo -> clamped global gather (matches reference)
            float cfx = clampf(fx), cfy = clampf(fy), cfz = clampf(fz);
            ix0 = (int)cfx;  iy0 = (int)cfy;  iz0 = (int)cfz;
            wx = cfx - (float)ix0;
            wy = cfy - (float)iy0;
            wz = cfz - (float)iz0;
            int ix1 = min(ix0 + 1, DMASK);
            int iy1 = min(iy0 + 1, DMASK);
            int iz1 = min(iz0 + 1, DMASK);
            int g00 = (ix0 << 14) + (iy0 << 7);
            int g01 = (ix0 << 14) + (iy1 << 7);
            int g10 = (ix1 << 14) + (iy0 << 7);
            int g11 = (ix1 << 14) + (iy1 << 7);
            v000 = __ldg(img + g00 + iz0);  v001 = __ldg(img + g00 + iz1);
            v010 = __ldg(img + g01 + iz0);  v011 = __ldg(img + g01 + iz1);
            v100 = __ldg(img + g10 + iz0);  v101 = __ldg(img + g10 + iz1);
            v110 = __ldg(img + g11 + iz0);  v111 = __ldg(img + g11 + iz1);
        }

        float c00 = v000 + wz * (v001 - v000);
        float c01 = v010 + wz * (v011 - v010);
        float c10 = v100 + wz * (v101 - v100);
        float c11 = v110 + wz * (v111 - v110);
        float c0  = c00 + wy * (c01 - c00);
        float c1  = c10 + wy * (c11 - c10);
        outb[vid] = c0 + wx * (c1 - c0);
    }
}

extern "C" void kernel_launch(void* const* d_in, const int* in_sizes, int n_in,
                              void* d_out, int out_size)
{
    const float* ddf   = (const float*)d_in[0];
    const float* image = (const float*)d_in[1];
    float* out = (float*)d_out;

    size_t smem = TILE_ELEMS * sizeof(float);   // 71400 B
    cudaFuncSetAttribute(warp_kernel,
                         cudaFuncAttributeMaxDynamicSharedMemorySize, (int)smem);

    warp_kernel<<<2048, BLOCK, smem>>>(ddf, image, out);
}